// round 14
// baseline (speedup 1.0000x reference)
#include <cuda_runtime.h>
#include <math.h>

#define TT 128
#define HH 64
#define WW 64
#define HW 4096

// ---------------- scratch (device globals: allocation-free rule) ----------------
__device__ float g_ys1[TT * 32 * HW];           // layer-1 hidden sequence
__device__ float g_ys2[TT * 64 * HW];           // layer-2 hidden sequence
__device__ float g_p2r[4 * 256 * HW];           // layer-2 partial ring (4 steps)
__device__ float g_c1[32 * HW];
__device__ float g_c2[64 * HW];
__device__ float g_zero[64 * HW];               // zero at load, never written
__device__ float g_wx1 [4 * 8  * 288];          // L1 x: ci 0-2 (pad 8)
__device__ float g_wh1 [4 * 32 * 288];          // L1 h: ci 3-34
__device__ float g_wc1x[8 * 32 * 288];          // L2 ci 0-31  (x = ys1)
__device__ float g_wc1h[8 * 16 * 288];          // L2 ci 32-47 (h 0-15)
__device__ float g_wc2h[8 * 48 * 288];          // L2 ci 48-95 (h 16-63)
__device__ int   g_cntA[TT], g_cntC1[TT], g_cntC2[TT];

__device__ __forceinline__ float sigf(float x) { return 1.0f / (1.0f + expf(-x)); }

// packed f32x2 helpers (sm_103a FFMA2 — PTX-only)
__device__ __forceinline__ unsigned long long splat2(float v) {
    unsigned long long d;
    asm("mov.b64 %0, {%1, %1};" : "=l"(d) : "f"(v));
    return d;
}
__device__ __forceinline__ void ffma2(unsigned long long& d, unsigned long long a, unsigned long long b) {
    asm("fma.rn.f32x2 %0, %1, %2, %0;" : "+l"(d) : "l"(a), "l"(b));
}
__device__ __forceinline__ float2 up2(unsigned long long v) {
    float2 f;
    asm("mov.b64 {%0, %1}, %2;" : "=f"(f.x), "=f"(f.y) : "l"(v));
    return f;
}

// ---------------- flag sync ------------------------------------------------------
__device__ __forceinline__ void waitfor(const int* cnt, int target) {
    if (threadIdx.x == 0) {
        while (*(volatile const int*)cnt < target) __nanosleep(64);
        __threadfence();
    }
    __syncthreads();
}
__device__ __forceinline__ void arrive(int* cnt) {
    __threadfence();
    __syncthreads();
    if (threadIdx.x == 0) atomicAdd(cnt, 1);
}

// ---------------- zero states + flags (graph replays re-run this) ----------------
__global__ void zero_c_kernel() {
    int i = blockIdx.x * blockDim.x + threadIdx.x;
    if (i < 32 * HW) g_c1[i] = 0.0f;
    if (i < 64 * HW) g_c2[i] = 0.0f;
    if (i < TT) { g_cntA[i] = 0; g_cntC1[i] = 0; g_cntC2[i] = 0; }
}

// ------- weight reshape: w[4*CHID][TOTC][9], ci slice -> [coblk][ci][9][4][8] ----
template <int CHID, int TOTC, int CI0, int CIC, int CIPAD>
__global__ void reshape_kernel(const float* __restrict__ w, float* __restrict__ wr) {
    const int n = (CHID / 8) * CIPAD * 288;
    for (int i = blockIdx.x * blockDim.x + threadIdx.x; i < n; i += gridDim.x * blockDim.x) {
        int co   = i & 7;
        int g    = (i >> 3) & 3;
        int tap  = (i >> 5) % 9;
        int rest = i / 288;
        int ci   = rest % CIPAD;
        int cb   = rest / CIPAD;
        float v = 0.0f;
        if (ci < CIC) v = w[((g * CHID + cb * 8 + co) * TOTC + CI0 + ci) * 9 + tap];
        wr[i] = v;
    }
}

// ---------------- 4-px accumulate core (f32x2 packed) ----------------------------
// tile: 4 rows x 64 cols x 8 co (x4 gates); thread: 4 px, 4 co-pairs x 4 gates.
template <int CINR, int NCHUNK>
__device__ __forceinline__ void accum4(
    unsigned long long (&acc)[4][2][4],
    const float* __restrict__ x,           // [>=CINR][HW]
    const float* __restrict__ wr,          // [coblk][NCHUNK*8 ci][9][4][8]
    int blk, float* smem)
{
    float (*psm)[6][68] = (float(*)[6][68])smem;
    float (*wsm)[9][4][8] = (float(*)[9][4][8])(smem + 8 * 6 * 68);

    const int tid     = threadIdx.x;
    const int co_half = tid >> 6;
    const int pid     = tid & 63;
    const int row     = pid >> 4;
    const int x0      = (pid & 15) << 2;
    const int co_blk  = blk >> 4;
    const int y0      = (blk & 15) << 2;

    const float* wblk = wr + (size_t)co_blk * (NCHUNK * 2304);

    for (int ch = 0; ch < NCHUNK; ch++) {
        {
            const float* src = wblk + ch * 2304;
            float* dst = &wsm[0][0][0][0];
            #pragma unroll
            for (int k = 0; k < 18; k++) dst[tid + k * 128] = src[tid + k * 128];
        }
        for (int i = tid; i < 8 * 6 * 66; i += 128) {
            int col = i % 66;
            int r   = (i / 66) % 6;
            int ci  = i / 396;
            int cig = ch * 8 + ci;
            int y   = y0 - 1 + r;
            int xx  = col - 1;
            float v = 0.0f;
            if (cig < CINR && (unsigned)y < HH && (unsigned)xx < WW)
                v = x[(size_t)cig * HW + y * WW + xx];
            psm[ci][r][col] = v;
        }
        __syncthreads();

        #pragma unroll
        for (int ci = 0; ci < 8; ci++) {
            #pragma unroll
            for (int ky = 0; ky < 3; ky++) {
                unsigned long long sp[6];
                #pragma unroll
                for (int c2 = 0; c2 < 6; c2++)
                    sp[c2] = splat2(psm[ci][row + ky][x0 + c2]);
                #pragma unroll
                for (int kx = 0; kx < 3; kx++) {
                    #pragma unroll
                    for (int g = 0; g < 4; g++) {
                        const ulonglong2 wp =
                            *(const ulonglong2*)&wsm[ci][ky * 3 + kx][g][co_half * 4];
                        #pragma unroll
                        for (int j = 0; j < 4; j++) {
                            ffma2(acc[g][0][j], wp.x, sp[kx + j]);
                            ffma2(acc[g][1][j], wp.y, sp[kx + j]);
                        }
                    }
                }
            }
        }
        __syncthreads();
    }
}

// ---------------- epilogues ------------------------------------------------------
// raw partial write: out[(g*64+co)][HW] = acc  (C1)
__device__ __forceinline__ void epi_partial(
    unsigned long long (&acc)[4][2][4], float* __restrict__ out, int blk)
{
    const int tid = threadIdx.x, co_half = tid >> 6, pid = tid & 63;
    const int row = pid >> 4, x0 = (pid & 15) << 2;
    const int co_blk = blk >> 4, y0 = (blk & 15) << 2;
    const int pos = (y0 + row) * WW + x0;
    #pragma unroll
    for (int g = 0; g < 4; g++)
        #pragma unroll
        for (int cl = 0; cl < 4; cl++) {
            const int co = co_blk * 8 + co_half * 4 + cl;
            float v[4];
            #pragma unroll
            for (int j = 0; j < 4; j++) {
                float2 f = up2(acc[g][cl >> 1][j]);
                v[j] = (cl & 1) ? f.y : f.x;
            }
            *(float4*)(out + ((size_t)g * 64 + co) * HW + pos) =
                make_float4(v[0], v[1], v[2], v[3]);
        }
}

// LSTM epilogue: gates = acc + bias (+ partial via __ldcg if PARTIAL)
template <int CHID, bool PARTIAL>
__device__ __forceinline__ void epi_lstm(
    unsigned long long (&acc)[4][2][4],
    const float* __restrict__ part, const float* __restrict__ bias,
    float* __restrict__ hout, float* __restrict__ cst, int blk)
{
    const int tid = threadIdx.x, co_half = tid >> 6, pid = tid & 63;
    const int row = pid >> 4, x0 = (pid & 15) << 2;
    const int co_blk = blk >> 4, y0 = (blk & 15) << 2;
    const int pos = (y0 + row) * WW + x0;
    #pragma unroll
    for (int cl = 0; cl < 4; cl++) {
        const int co = co_blk * 8 + co_half * 4 + cl;
        float gv[4][4];
        #pragma unroll
        for (int g = 0; g < 4; g++) {
            const float bv = bias[g * CHID + co];
            float pl[4] = {0.f, 0.f, 0.f, 0.f};
            if constexpr (PARTIAL) {
                float4 pv = __ldcg((const float4*)(part + ((size_t)g * CHID + co) * HW + pos));
                pl[0] = pv.x; pl[1] = pv.y; pl[2] = pv.z; pl[3] = pv.w;
            }
            #pragma unroll
            for (int j = 0; j < 4; j++) {
                float2 f = up2(acc[g][cl >> 1][j]);
                gv[g][j] = ((cl & 1) ? f.y : f.x) + bv + pl[j];
            }
        }
        float* cp = cst  + (size_t)co * HW + pos;
        float* hp = hout + (size_t)co * HW + pos;
        float4 cold = *(const float4*)cp;
        float cia[4] = {cold.x, cold.y, cold.z, cold.w};
        float cv[4], hv[4];
        #pragma unroll
        for (int j = 0; j < 4; j++) {
            float iv = sigf(gv[0][j]);
            float fv = sigf(gv[1][j]);
            float ov = sigf(gv[2][j]);
            float gg = tanhf(gv[3][j]);
            float cn = fv * cia[j] + iv * gg;
            cv[j] = cn;
            hv[j] = ov * tanhf(cn);
        }
        *(float4*)cp = make_float4(cv[0], cv[1], cv[2], cv[3]);
        *(float4*)hp = make_float4(hv[0], hv[1], hv[2], hv[3]);
    }
}

// ---------------- persistent 3-chain pipeline ------------------------------------
// blocks [0,64):    A  : L1 x-conv (1ch) + L1 h-conv (4ch) + LSTM -> ys1
// blocks [64,192):  C1 : L2 ci 0-31 (ys1, 4ch) + ci 32-47 (ys2, 2ch) -> partial
// blocks [192,320): C2 : L2 ci 48-95 (ys2, 6ch) + partial + bias -> LSTM -> ys2
__global__ void __launch_bounds__(128, 4) persist_kernel(
    const float* __restrict__ input, const float* __restrict__ b1,
    const float* __restrict__ b2)
{
    __shared__ __align__(16) float smem[8 * 6 * 68 + 2304];
    const int b = blockIdx.x;

    if (b < 64) {
        for (int t = 0; t < TT; t++) {
            unsigned long long acc[4][2][4];
            #pragma unroll
            for (int g = 0; g < 4; g++)
                #pragma unroll
                for (int p = 0; p < 2; p++)
                    #pragma unroll
                    for (int j = 0; j < 4; j++) acc[g][p][j] = 0ull;
            accum4<3, 1>(acc, input + (size_t)t * 3 * HW, g_wx1, b, smem);
            if (t) waitfor(&g_cntA[t - 1], 64);
            accum4<32, 4>(acc, t ? g_ys1 + (size_t)(t - 1) * 32 * HW : g_zero,
                          g_wh1, b, smem);
            epi_lstm<32, false>(acc, nullptr, b1,
                                g_ys1 + (size_t)t * 32 * HW, g_c1, b);
            arrive(&g_cntA[t]);
        }
    } else if (b < 192) {
        const int bb = b - 64;
        for (int s = 0; s < TT; s++) {
            unsigned long long acc[4][2][4];
            #pragma unroll
            for (int g = 0; g < 4; g++)
                #pragma unroll
                for (int p = 0; p < 2; p++)
                    #pragma unroll
                    for (int j = 0; j < 4; j++) acc[g][p][j] = 0ull;
            waitfor(&g_cntA[s], 64);
            accum4<32, 4>(acc, g_ys1 + (size_t)s * 32 * HW, g_wc1x, bb, smem);
            if (s) waitfor(&g_cntC2[s - 1], 128);
            accum4<16, 2>(acc, s ? g_ys2 + (size_t)(s - 1) * 64 * HW : g_zero,
                          g_wc1h, bb, smem);
            epi_partial(acc, g_p2r + (size_t)(s & 3) * 256 * HW, bb);
            arrive(&g_cntC1[s]);
        }
    } else {
        const int bb = b - 192;
        for (int s = 0; s < TT; s++) {
            unsigned long long acc[4][2][4];
            #pragma unroll
            for (int g = 0; g < 4; g++)
                #pragma unroll
                for (int p = 0; p < 2; p++)
                    #pragma unroll
                    for (int j = 0; j < 4; j++) acc[g][p][j] = 0ull;
            if (s) waitfor(&g_cntC2[s - 1], 128);
            accum4<48, 6>(acc, (s ? g_ys2 + (size_t)(s - 1) * 64 * HW : g_zero) + 16 * HW,
                          g_wc2h, bb, smem);
            waitfor(&g_cntC1[s], 128);
            epi_lstm<64, true>(acc, g_p2r + (size_t)(s & 3) * 256 * HW, b2,
                               g_ys2 + (size_t)s * 64 * HW, g_c2, bb);
            arrive(&g_cntC2[s]);
        }
    }
}

// ---------------- FC head --------------------------------------------------------
__global__ void fc_kernel(const float* __restrict__ ys2, const float* __restrict__ fcw,
                          const float* __restrict__ fcb, float* __restrict__ out) {
    const int t = blockIdx.y;
    const int j = blockIdx.x;
    const float* a = ys2 + (size_t)t * 64 * HW;
    const float* w = fcw + (size_t)j * 64 * HW;
    float s = 0.0f;
    const int n = 64 * HW;
    for (int i = threadIdx.x * 4; i < n; i += blockDim.x * 4) {
        float4 av = *(const float4*)(a + i);
        float4 bv = *(const float4*)(w + i);
        s += av.x * bv.x + av.y * bv.y + av.z * bv.z + av.w * bv.w;
    }
    __shared__ float red[32];
    for (int off = 16; off; off >>= 1) s += __shfl_down_sync(0xffffffffu, s, off);
    if ((threadIdx.x & 31) == 0) red[threadIdx.x >> 5] = s;
    __syncthreads();
    if (threadIdx.x < 32) {
        s = (threadIdx.x < (blockDim.x >> 5)) ? red[threadIdx.x] : 0.0f;
        for (int off = 16; off; off >>= 1) s += __shfl_down_sync(0xffffffffu, s, off);
        if (threadIdx.x == 0) out[t * 6 + j] = s + fcb[j];
    }
}

// ---------------- final state copy-out -------------------------------------------
__global__ void copy_out_kernel(float* __restrict__ out) {
    const int i = blockIdx.x * blockDim.x + threadIdx.x;
    float* o = out + TT * 6;
    if (i < 32 * HW) {
        o[i]           = g_ys1[127 * 32 * HW + i];
        o[32 * HW + i] = g_c1[i];
    }
    if (i < 64 * HW) {
        o[64 * HW + i]           = g_ys2[(size_t)127 * 64 * HW + i];
        o[64 * HW + 64 * HW + i] = g_c2[i];
    }
}

// ---------------- launch (single stream, no stream/event objects) ----------------
extern "C" void kernel_launch(void* const* d_in, const int* in_sizes, int n_in,
                              void* d_out, int out_size) {
    const float* input = (const float*)d_in[0];
    const float* w1    = (const float*)d_in[1];
    const float* b1    = (const float*)d_in[2];
    const float* w2    = (const float*)d_in[3];
    const float* b2    = (const float*)d_in[4];
    const float* fcw   = (const float*)d_in[5];
    const float* fcb   = (const float*)d_in[6];
    float* out = (float*)d_out;

    float *ys2, *wx1, *wh1, *wc1x, *wc1h, *wc2h;
    cudaGetSymbolAddress((void**)&ys2,  g_ys2);
    cudaGetSymbolAddress((void**)&wx1,  g_wx1);
    cudaGetSymbolAddress((void**)&wh1,  g_wh1);
    cudaGetSymbolAddress((void**)&wc1x, g_wc1x);
    cudaGetSymbolAddress((void**)&wc1h, g_wc1h);
    cudaGetSymbolAddress((void**)&wc2h, g_wc2h);

    zero_c_kernel<<<1024, 256>>>();
    reshape_kernel<32, 35, 0,  3,  8 ><<<32,  256>>>(w1, wx1);
    reshape_kernel<32, 35, 3,  32, 32><<<128, 256>>>(w1, wh1);
    reshape_kernel<64, 96, 0,  32, 32><<<256, 256>>>(w2, wc1x);
    reshape_kernel<64, 96, 32, 16, 16><<<128, 256>>>(w2, wc1h);
    reshape_kernel<64, 96, 48, 48, 48><<<384, 256>>>(w2, wc2h);

    // all 128 timesteps, both layers, x-convs fused: one persistent pipeline
    persist_kernel<<<320, 128>>>(input, b1, b2);

    dim3 fg(6, TT);
    fc_kernel<<<fg, 256>>>(ys2, fcw, fcb, out);
    copy_out_kernel<<<1024, 256>>>(out);
}

// round 16
// speedup vs baseline: 2.2522x; 2.2522x over previous
#include <cuda_runtime.h>
#include <math.h>

#define TT 128
#define HH 64
#define WW 64
#define HW 4096

// ---------------- scratch (device globals: allocation-free rule) ----------------
__device__ float g_ys1[TT * 32 * HW];           // layer-1 hidden sequence
__device__ float g_ys2[TT * 64 * HW];           // layer-2 hidden sequence
__device__ float g_z1 [TT * 128 * HW];          // layer-1 x-part preactivations
__device__ float g_z2r[4 * 256 * HW];           // layer-2 x-part ring (4 steps)
__device__ float g_c1[32 * HW];
__device__ float g_c2[64 * HW];
__device__ float g_zero[64 * HW];               // zero at load, never written
__device__ float g_wx1[4 * 8  * 288];           // [coblk][ci][9][4][8]
__device__ float g_wh1[4 * 32 * 288];
__device__ float g_wx2[8 * 32 * 288];
__device__ float g_wh2[8 * 64 * 288];
__device__ int   g_cntA[TT], g_cntB[TT], g_cntC[TT];   // chain counters
__device__ int   g_cntCrow[TT * 32];                   // per-row-group C counters

__device__ __forceinline__ float sigf(float x) { return 1.0f / (1.0f + expf(-x)); }

// packed f32x2 helpers (sm_103a FFMA2 — PTX-only)
__device__ __forceinline__ unsigned long long splat2(float v) {
    unsigned long long d;
    asm("mov.b64 %0, {%1, %1};" : "=l"(d) : "f"(v));
    return d;
}
__device__ __forceinline__ void ffma2(unsigned long long& d, unsigned long long a, unsigned long long b) {
    asm("fma.rn.f32x2 %0, %1, %2, %0;" : "+l"(d) : "l"(a), "l"(b));
}
__device__ __forceinline__ float2 up2(unsigned long long v) {
    float2 f;
    asm("mov.b64 {%0, %1}, %2;" : "=f"(f.x), "=f"(f.y) : "l"(v));
    return f;
}

// ---------------- flag sync ------------------------------------------------------
__device__ __forceinline__ void waitfor(const int* cnt, int target) {
    if (threadIdx.x == 0) {
        while (*(volatile const int*)cnt < target) __nanosleep(64);
        __threadfence();
    }
    __syncthreads();
}
// wait 3 row-group counters of step s-1 (clamped neighborhood), each >= 8
__device__ __forceinline__ void wait_rows(const int* base, int rg) {
    if (threadIdx.x == 0) {
        const int lo = rg > 0 ? rg - 1 : 0;
        const int hi = rg < 31 ? rg + 1 : 31;
        for (int r = lo; r <= hi; r++) {
            const volatile int* p = (const volatile int*)(base + r);
            while (*p < 8) __nanosleep(64);
        }
        __threadfence();
    }
    __syncthreads();
}
__device__ __forceinline__ void arrive(int* cnt) {
    __threadfence();
    __syncthreads();
    if (threadIdx.x == 0) atomicAdd(cnt, 1);
}
__device__ __forceinline__ void arrive2(int* cnt, int* cnt2) {
    __threadfence();
    __syncthreads();
    if (threadIdx.x == 0) { atomicAdd(cnt, 1); atomicAdd(cnt2, 1); }
}

// ---------------- zero states + flags (graph replays re-run this) ----------------
__global__ void zero_c_kernel() {
    int i = blockIdx.x * blockDim.x + threadIdx.x;
    if (i < 32 * HW) g_c1[i] = 0.0f;
    if (i < 64 * HW) g_c2[i] = 0.0f;
    if (i < TT) { g_cntA[i] = 0; g_cntB[i] = 0; g_cntC[i] = 0; }
    if (i < TT * 32) g_cntCrow[i] = 0;
}

// ------- weight reshape: w[4*CHID][TOTC][9], ci slice -> [coblk][ci][9][4][8] ----
template <int CHID, int TOTC, int CI0, int CIC, int CIPAD>
__global__ void reshape_kernel(const float* __restrict__ w, float* __restrict__ wr) {
    const int n = (CHID / 8) * CIPAD * 288;
    for (int i = blockIdx.x * blockDim.x + threadIdx.x; i < n; i += gridDim.x * blockDim.x) {
        int co   = i & 7;
        int g    = (i >> 3) & 3;
        int tap  = (i >> 5) % 9;
        int rest = i / 288;
        int ci   = rest % CIPAD;
        int cb   = rest / CIPAD;
        float v = 0.0f;
        if (ci < CIC) v = w[((g * CHID + cb * 8 + co) * TOTC + CI0 + ci) * 9 + tap];
        wr[i] = v;
    }
}

// ---------------- unified COB=8 conv core (f32x2 packed) -------------------------
// 128 threads; tile ROWS rows x 64 cols x 8 co (x4 gates); per-thread PXT=ROWS px.
// LSTM: gates = acc + z(zio); update c,h.  !LSTM: out = acc + bias.
// ZCG: load z via __ldcg (L2) — required for ring-buffer reuse (L1 staleness).
template <int CINR, int NCHUNK, int CHID, int ROWS, bool LSTM, bool ZCG>
__device__ __forceinline__ void core8(
    const float* __restrict__ x,
    const float* __restrict__ zio,
    const float* __restrict__ bias,
    float* __restrict__ out,
    float* __restrict__ cst,
    const float* __restrict__ wr, int blk, float* smem)
{
    constexpr int PXT    = ROWS;
    constexpr int ROWBLK = 64 / ROWS;
    constexpr int GPR    = 64 / PXT;
    constexpr int PS     = 8 * (ROWS + 2) * 68;

    float (*psm)[ROWS + 2][68] = (float(*)[ROWS + 2][68])smem;
    float (*wsm)[9][4][8]      = (float(*)[9][4][8])(smem + PS);

    const int tid     = threadIdx.x;
    const int co_half = tid >> 6;
    const int pid     = tid & 63;
    const int row     = pid / GPR;
    const int x0      = (pid % GPR) * PXT;

    const int co_blk = blk / ROWBLK;
    const int y0     = (blk % ROWBLK) * ROWS;

    unsigned long long acc[4][2][PXT];
    #pragma unroll
    for (int g = 0; g < 4; g++)
        #pragma unroll
        for (int p = 0; p < 2; p++)
            #pragma unroll
            for (int j = 0; j < PXT; j++) acc[g][p][j] = 0ull;

    const float* wblk = wr + (size_t)co_blk * (NCHUNK * 2304);

    for (int ch = 0; ch < NCHUNK; ch++) {
        {
            const float* src = wblk + ch * 2304;
            float* dst = &wsm[0][0][0][0];
            #pragma unroll
            for (int k = 0; k < 18; k++) dst[tid + k * 128] = src[tid + k * 128];
        }
        constexpr int NST = 8 * (ROWS + 2) * 66;
        for (int i = tid; i < NST; i += 128) {
            int col = i % 66;
            int r   = (i / 66) % (ROWS + 2);
            int ci  = i / (66 * (ROWS + 2));
            int cig = ch * 8 + ci;
            int y   = y0 - 1 + r;
            int xx  = col - 1;
            float v = 0.0f;
            if (cig < CINR && (unsigned)y < HH && (unsigned)xx < WW)
                v = x[(size_t)cig * HW + y * WW + xx];
            psm[ci][r][col] = v;
        }
        __syncthreads();

        #pragma unroll
        for (int ci = 0; ci < 8; ci++) {
            #pragma unroll
            for (int ky = 0; ky < 3; ky++) {
                unsigned long long sp[PXT + 2];
                #pragma unroll
                for (int c2 = 0; c2 < PXT + 2; c2++)
                    sp[c2] = splat2(psm[ci][row + ky][x0 + c2]);
                #pragma unroll
                for (int kx = 0; kx < 3; kx++) {
                    #pragma unroll
                    for (int g = 0; g < 4; g++) {
                        const ulonglong2 wp =
                            *(const ulonglong2*)&wsm[ci][ky * 3 + kx][g][co_half * 4];
                        #pragma unroll
                        for (int j = 0; j < PXT; j++) {
                            ffma2(acc[g][0][j], wp.x, sp[kx + j]);
                            ffma2(acc[g][1][j], wp.y, sp[kx + j]);
                        }
                    }
                }
            }
        }
        __syncthreads();
    }

    const int pos = (y0 + row) * WW + x0;

    if constexpr (!LSTM) {
        #pragma unroll
        for (int g = 0; g < 4; g++)
            #pragma unroll
            for (int cl = 0; cl < 4; cl++) {
                const int co  = co_blk * 8 + co_half * 4 + cl;
                const int chn = g * CHID + co;
                const float bv = bias[chn];
                float vals[PXT];
                #pragma unroll
                for (int j = 0; j < PXT; j++) {
                    float2 f = up2(acc[g][cl >> 1][j]);
                    vals[j] = ((cl & 1) ? f.y : f.x) + bv;
                }
                float* dst = out + (size_t)chn * HW + pos;
                if constexpr (PXT == 4)
                    *(float4*)dst = make_float4(vals[0], vals[1], vals[2], vals[3]);
                else
                    *(float2*)dst = make_float2(vals[0], vals[1]);
            }
    } else {
        #pragma unroll
        for (int cl = 0; cl < 4; cl++) {
            const int co = co_blk * 8 + co_half * 4 + cl;
            float gv[4][PXT];
            #pragma unroll
            for (int g = 0; g < 4; g++) {
                const float* zp = zio + ((size_t)g * CHID + co) * HW + pos;
                float zl[PXT];
                if constexpr (PXT == 4) {
                    float4 v = ZCG ? __ldcg((const float4*)zp) : *(const float4*)zp;
                    zl[0] = v.x; zl[1] = v.y; zl[2] = v.z; zl[3] = v.w;
                } else {
                    float2 v = ZCG ? __ldcg((const float2*)zp) : *(const float2*)zp;
                    zl[0] = v.x; zl[1] = v.y;
                }
                #pragma unroll
                for (int j = 0; j < PXT; j++) {
                    float2 f = up2(acc[g][cl >> 1][j]);
                    gv[g][j] = ((cl & 1) ? f.y : f.x) + zl[j];
                }
            }
            float* cp = cst + (size_t)co * HW + pos;
            float* hp = out + (size_t)co * HW + pos;
            float cold[PXT];
            if constexpr (PXT == 4) {
                float4 v = *(const float4*)cp;
                cold[0] = v.x; cold[1] = v.y; cold[2] = v.z; cold[3] = v.w;
            } else {
                float2 v = *(const float2*)cp;
                cold[0] = v.x; cold[1] = v.y;
            }
            float cv[PXT], hv[PXT];
            #pragma unroll
            for (int j = 0; j < PXT; j++) {
                float iv = sigf(gv[0][j]);
                float fv = sigf(gv[1][j]);
                float ov = sigf(gv[2][j]);
                float gg = tanhf(gv[3][j]);
                float cn = fv * cold[j] + iv * gg;
                cv[j] = cn;
                hv[j] = ov * tanhf(cn);
            }
            if constexpr (PXT == 4) {
                *(float4*)cp = make_float4(cv[0], cv[1], cv[2], cv[3]);
                *(float4*)hp = make_float4(hv[0], hv[1], hv[2], hv[3]);
            } else {
                *(float2*)cp = make_float2(cv[0], cv[1]);
                *(float2*)hp = make_float2(hv[0], hv[1]);
            }
        }
    }
}

// ---------------- batched layer-1 x-part over all T (blockIdx.z = t) -------------
__global__ void __launch_bounds__(128) zx1_kernel(
    const float* __restrict__ input, const float* __restrict__ b1)
{
    __shared__ __align__(16) float smem[8 * 6 * 68 + 2304];
    core8<3, 1, 32, 4, false, false>(input + (size_t)blockIdx.z * 3 * HW,
                                     nullptr, b1,
                                     g_z1 + (size_t)blockIdx.z * 128 * HW,
                                     nullptr, g_wx1, blockIdx.x, smem);
}

// ---------------- persistent pipeline kernel -------------------------------------
// blocks [0,64):   A chain: L1 h-step t           (4 chunks, 4-px)
// blocks [64,192): B chain: L2 x-conv step s       (4 chunks, 4-px) -> z2 ring
// blocks [192,448):C chain: L2 h-step s + LSTM     (8 chunks, 2-px),
//                  neighborhood row-group waits instead of full-grid barrier.
__global__ void __launch_bounds__(128, 4) persist_kernel(const float* __restrict__ b2) {
    __shared__ __align__(16) float smem[8 * 6 * 68 + 2304];
    const int b = blockIdx.x;
    if (b < 64) {
        for (int t = 0; t < TT; t++) {
            if (t) waitfor(&g_cntA[t - 1], 64);
            const float* hin = t ? g_ys1 + (size_t)(t - 1) * 32 * HW : g_zero;
            core8<32, 4, 32, 4, true, false>(hin, g_z1 + (size_t)t * 128 * HW, nullptr,
                                             g_ys1 + (size_t)t * 32 * HW, g_c1, g_wh1, b, smem);
            arrive(&g_cntA[t]);
        }
    } else if (b < 192) {
        const int bb = b - 64;
        for (int s = 0; s < TT; s++) {
            waitfor(&g_cntA[s], 64);
            if (s >= 4) waitfor(&g_cntC[s - 4], 256);      // ring slot reuse (global)
            core8<32, 4, 64, 4, false, false>(g_ys1 + (size_t)s * 32 * HW, nullptr, b2,
                                              g_z2r + (size_t)(s & 3) * 256 * HW,
                                              nullptr, g_wx2, bb, smem);
            arrive(&g_cntB[s]);
        }
    } else {
        const int bb = b - 192;
        const int rg = bb & 31;                            // row-group of this block
        for (int s = 0; s < TT; s++) {
            waitfor(&g_cntB[s], 128);
            if (s) wait_rows(&g_cntCrow[(s - 1) * 32], rg);
            const float* hin = s ? g_ys2 + (size_t)(s - 1) * 64 * HW : g_zero;
            core8<64, 8, 64, 2, true, true>(hin, g_z2r + (size_t)(s & 3) * 256 * HW, nullptr,
                                            g_ys2 + (size_t)s * 64 * HW, g_c2, g_wh2, bb, smem);
            arrive2(&g_cntC[s], &g_cntCrow[s * 32 + rg]);
        }
    }
}

// ---------------- FC head --------------------------------------------------------
__global__ void fc_kernel(const float* __restrict__ ys2, const float* __restrict__ fcw,
                          const float* __restrict__ fcb, float* __restrict__ out) {
    const int t = blockIdx.y;
    const int j = blockIdx.x;
    const float* a = ys2 + (size_t)t * 64 * HW;
    const float* w = fcw + (size_t)j * 64 * HW;
    float s = 0.0f;
    const int n = 64 * HW;
    for (int i = threadIdx.x * 4; i < n; i += blockDim.x * 4) {
        float4 av = *(const float4*)(a + i);
        float4 bv = *(const float4*)(w + i);
        s += av.x * bv.x + av.y * bv.y + av.z * bv.z + av.w * bv.w;
    }
    __shared__ float red[32];
    for (int off = 16; off; off >>= 1) s += __shfl_down_sync(0xffffffffu, s, off);
    if ((threadIdx.x & 31) == 0) red[threadIdx.x >> 5] = s;
    __syncthreads();
    if (threadIdx.x < 32) {
        s = (threadIdx.x < (blockDim.x >> 5)) ? red[threadIdx.x] : 0.0f;
        for (int off = 16; off; off >>= 1) s += __shfl_down_sync(0xffffffffu, s, off);
        if (threadIdx.x == 0) out[t * 6 + j] = s + fcb[j];
    }
}

// ---------------- final state copy-out -------------------------------------------
__global__ void copy_out_kernel(float* __restrict__ out) {
    const int i = blockIdx.x * blockDim.x + threadIdx.x;
    float* o = out + TT * 6;
    if (i < 32 * HW) {
        o[i]           = g_ys1[127 * 32 * HW + i];
        o[32 * HW + i] = g_c1[i];
    }
    if (i < 64 * HW) {
        o[64 * HW + i]           = g_ys2[(size_t)127 * 64 * HW + i];
        o[64 * HW + 64 * HW + i] = g_c2[i];
    }
}

// ---------------- launch (single stream, no stream/event objects) ----------------
extern "C" void kernel_launch(void* const* d_in, const int* in_sizes, int n_in,
                              void* d_out, int out_size) {
    const float* input = (const float*)d_in[0];
    const float* w1    = (const float*)d_in[1];
    const float* b1    = (const float*)d_in[2];
    const float* w2    = (const float*)d_in[3];
    const float* b2    = (const float*)d_in[4];
    const float* fcw   = (const float*)d_in[5];
    const float* fcb   = (const float*)d_in[6];
    float* out = (float*)d_out;

    float *ys2, *wx1, *wh1, *wx2, *wh2;
    cudaGetSymbolAddress((void**)&ys2, g_ys2);
    cudaGetSymbolAddress((void**)&wx1, g_wx1);
    cudaGetSymbolAddress((void**)&wh1, g_wh1);
    cudaGetSymbolAddress((void**)&wx2, g_wx2);
    cudaGetSymbolAddress((void**)&wh2, g_wh2);

    zero_c_kernel<<<1024, 256>>>();
    reshape_kernel<32, 35, 0,  3,  8 ><<<32,  256>>>(w1, wx1);
    reshape_kernel<32, 35, 3,  32, 32><<<128, 256>>>(w1, wh1);
    reshape_kernel<64, 96, 0,  32, 32><<<256, 256>>>(w2, wx2);
    reshape_kernel<64, 96, 32, 64, 64><<<512, 256>>>(w2, wh2);

    // layer-1 x-part for all T (batched): 4 co-blk x 16 row-blk
    zx1_kernel<<<dim3(64, 1, TT), 128>>>(input, b1);

    // all 128 timesteps, both layers: one persistent flag-synced pipeline
    persist_kernel<<<448, 128>>>(b2);

    dim3 fg(6, TT);
    fc_kernel<<<fg, 256>>>(ys2, fcw, fcb, out);
    copy_out_kernel<<<1024, 256>>>(out);
}